// round 4
// baseline (speedup 1.0000x reference)
#include <cuda_runtime.h>
#include <math.h>

#define NIMG   16
#define NANCH  8732
#define NCLS   80
#define NCLS1  81
#define KCAND  400
#define KOUT   200
#define CAP    16384
#define CLIPV  4.135166556742356f  /* log(1000/16) */

// ---------------- device scratch (no cudaMalloc allowed) ----------------
__device__ float g_cls[NIMG * NANCH * NCLS1];       // conv cls logits
__device__ float g_reg[NIMG * NANCH * 4];           // conv reg deltas
__device__ float g_scr[NIMG * NANCH * NCLS];        // thresholded softmax scores
__device__ unsigned int g_hist[NIMG * 65536];
__device__ unsigned int g_thr[NIMG];
__device__ int g_cnt[NIMG];
__device__ unsigned long long g_cand[NIMG * CAP];
__device__ float g_cbox[NIMG * KCAND * 4];
__device__ float g_cscore[NIMG * KCAND];
__device__ int g_ccls[NIMG * KCAND];
__device__ int g_ckeep[NIMG * KCAND];

// ---------------- zero hist / counters ----------------
__global__ void zero_kernel() {
    int i = blockIdx.x * blockDim.x + threadIdx.x;
    if (i < NIMG * 65536) g_hist[i] = 0u;
    if (i < NIMG) g_cnt[i] = 0;
}

// ---------------- implicit-im2col conv as tiled SGEMM ----------------
// Kahan-compensated chunk accumulation: per 16-k chunk accumulate into a
// fresh f32 accumulator (error ~sqrt(16)*eps), then compensated-merge into
// the running total. Total error ~1e-7 abs, independent of K.
// out[b][anchor][t] with anchor = base + (y*W+x)*an + oc/tl, t = oc%tl
__global__ void conv_head(const float* __restrict__ x, const float* __restrict__ w,
                          const float* __restrict__ bias, float* __restrict__ out,
                          int C, int H, int W, int OC, int an, int tl, int base)
{
    const int HW = H * W;
    const int N  = NIMG * HW;
    const int K  = C * 9;          // always multiple of 16 for C in {256,512,1024}

    __shared__ float As[16][64];   // [k][m]
    __shared__ float Bs[16][64];   // [k][n]

    const int tid = threadIdx.x;
    const int m0 = blockIdx.y * 64;
    const int n0 = blockIdx.x * 64;

    // ---- B-load thread geometry: fixed n per thread ----
    const int bn  = tid & 63;
    const int bkb = (tid >> 6) * 4;
    const int n   = n0 + bn;
    const bool nvalid = (n < N);
    int bimg = 0, py = 0, px = 0;
    if (nvalid) { bimg = n / HW; int rem = n - bimg * HW; py = rem / W; px = rem - py * W; }
    const float* xb = x + (size_t)bimg * C * HW;

    // ---- A-load geometry: fixed m per thread, 4 consecutive k ----
    const int am  = tid >> 2;
    const int akb = (tid & 3) * 4;
    const int wrow = m0 + am;
    const bool mvalid = (wrow < OC);
    const float* wptr = w + (size_t)wrow * K;

    const int tm = (tid >> 4) * 4;
    const int tn = (tid & 15) * 4;
    float acc[4][4] = {};
    float cmp[4][4] = {};

    for (int k0 = 0; k0 < K; k0 += 16) {
        float4 av = make_float4(0.f, 0.f, 0.f, 0.f);
        if (mvalid) av = *(const float4*)(wptr + k0 + akb);
        As[akb + 0][am] = av.x; As[akb + 1][am] = av.y;
        As[akb + 2][am] = av.z; As[akb + 3][am] = av.w;

#pragma unroll
        for (int i = 0; i < 4; i++) {
            int k  = k0 + bkb + i;
            int ic = k / 9;
            int r  = k - ic * 9;
            int ky = r / 3;
            int kx = r - ky * 3;
            int iy = py + ky - 1;
            int ix = px + kx - 1;
            float v = 0.f;
            if (nvalid && (unsigned)iy < (unsigned)H && (unsigned)ix < (unsigned)W)
                v = xb[(ic * H + iy) * W + ix];
            Bs[bkb + i][bn] = v;
        }
        __syncthreads();

        float ch[4][4] = {};
#pragma unroll
        for (int kk = 0; kk < 16; kk++) {
            float4 a = *(const float4*)&As[kk][tm];
            float4 b = *(const float4*)&Bs[kk][tn];
            ch[0][0] += a.x * b.x; ch[0][1] += a.x * b.y; ch[0][2] += a.x * b.z; ch[0][3] += a.x * b.w;
            ch[1][0] += a.y * b.x; ch[1][1] += a.y * b.y; ch[1][2] += a.y * b.z; ch[1][3] += a.y * b.w;
            ch[2][0] += a.z * b.x; ch[2][1] += a.z * b.y; ch[2][2] += a.z * b.z; ch[2][3] += a.z * b.w;
            ch[3][0] += a.w * b.x; ch[3][1] += a.w * b.y; ch[3][2] += a.w * b.z; ch[3][3] += a.w * b.w;
        }
        __syncthreads();

        // Kahan merge (register-only; explicit rn intrinsics prevent reassoc)
#pragma unroll
        for (int i = 0; i < 4; i++)
#pragma unroll
            for (int j = 0; j < 4; j++) {
                float y = __fsub_rn(ch[i][j], cmp[i][j]);
                float t = __fadd_rn(acc[i][j], y);
                cmp[i][j] = __fsub_rn(__fsub_rn(t, acc[i][j]), y);
                acc[i][j] = t;
            }
    }

#pragma unroll
    for (int i = 0; i < 4; i++) {
        int m = m0 + tm + i;
        if (m >= OC) continue;
        float bv = bias[m];
        int a_idx = m / tl;
        int t = m - a_idx * tl;
#pragma unroll
        for (int j = 0; j < 4; j++) {
            int nn = n0 + tn + j;
            if (nn >= N) continue;
            int bi = nn / HW;
            int rem = nn - bi * HW;
            int anchor = base + rem * an + a_idx;
            float v = __fadd_rn(__fadd_rn(acc[i][j], cmp[i][j]), bv);
            out[((size_t)bi * NANCH + anchor) * tl + t] = v;
        }
    }
}

// ---------------- softmax(81) + threshold -> scores [.,8732,80] ----------------
__global__ void softmax_kernel() {
    int gw = (blockIdx.x * blockDim.x + threadIdx.x) >> 5;
    int lane = threadIdx.x & 31;
    if (gw >= NIMG * NANCH) return;
    const float* row = g_cls + (size_t)gw * NCLS1;
    float x0 = row[lane];
    float x1 = row[lane + 32];
    float x2 = (lane < 17) ? row[lane + 64] : -3.4e38f;
    float m = fmaxf(x0, fmaxf(x1, x2));
    for (int o = 16; o; o >>= 1) m = fmaxf(m, __shfl_xor_sync(0xffffffffu, m, o));
    float e0 = expf(x0 - m), e1 = expf(x1 - m);
    float e2 = (lane < 17) ? expf(x2 - m) : 0.f;
    float s = e0 + e1 + e2;
    for (int o = 16; o; o >>= 1) s += __shfl_xor_sync(0xffffffffu, s, o);
    float* outp = g_scr + (size_t)gw * NCLS;
    if (lane >= 1) { float p = e0 / s; outp[lane - 1]  = (p > 0.01f) ? p : 0.f; }
    {               float p = e1 / s; outp[lane + 31] = (p > 0.01f) ? p : 0.f; }
    if (lane < 17) { float p = e2 / s; outp[lane + 63] = (p > 0.01f) ? p : 0.f; }
}

// ---------------- histogram on high-16 float bits ----------------
__global__ void hist_kernel() {
    int i = blockIdx.x * blockDim.x + threadIdx.x;
    if (i >= NIMG * NANCH * NCLS) return;
    unsigned b = __float_as_uint(g_scr[i]);
    if (b) {
        int img = i / (NANCH * NCLS);
        atomicAdd(&g_hist[img * 65536 + (b >> 16)], 1u);
    }
}

// find smallest bin B with count(bin >= B) >= KCAND; threshold = B<<16
__global__ void select_kernel() {
    __shared__ unsigned csum[256];
    int img = blockIdx.x, tid = threadIdx.x;
    const unsigned* h = g_hist + img * 65536;
    unsigned s = 0;
    for (int j = 0; j < 256; j++) s += h[tid * 256 + j];
    csum[tid] = s;
    __syncthreads();
    if (tid == 0) {
        unsigned cum = 0; int c;
        for (c = 255; c >= 0; c--) {
            if (cum + csum[c] >= KCAND) break;
            cum += csum[c];
        }
        unsigned T = 1u;
        if (c >= 0) {
            int b;
            for (b = c * 256 + 255; b >= c * 256; b--) {
                cum += h[b];
                if (cum >= KCAND) break;
            }
            if (b < c * 256) b = c * 256;
            T = ((unsigned)b) << 16;
            if (T == 0u) T = 1u;
        }
        g_thr[img] = T;
    }
}

__global__ void compact_kernel() {
    int i = blockIdx.x * blockDim.x + threadIdx.x;
    if (i >= NIMG * NANCH * NCLS) return;
    unsigned b = __float_as_uint(g_scr[i]);
    int img = i / (NANCH * NCLS);
    if (b >= g_thr[img]) {
        int p = atomicAdd(&g_cnt[img], 1);
        if (p < CAP) {
            unsigned fidx = (unsigned)(i - img * NANCH * NCLS);
            g_cand[img * CAP + p] =
                ((unsigned long long)b << 32) | (unsigned long long)(0xFFFFFFFFu - fidx);
        }
    }
}

// ---------------- sort candidates (desc score, asc idx), decode top-400 ----------------
// Decode replicates JAX rounding exactly: no FMA contraction.
__global__ void sort_decode_kernel(const float* __restrict__ priors) {
    extern __shared__ unsigned long long sk[];
    int img = blockIdx.x, tid = threadIdx.x, nt = blockDim.x;
    int cnt = g_cnt[img];
    if (cnt > CAP) cnt = CAP;
    for (int i = tid; i < CAP; i += nt)
        sk[i] = (i < cnt) ? g_cand[img * CAP + i] : 0ULL;
    __syncthreads();

    for (int k = 2; k <= CAP; k <<= 1) {
        for (int j = k >> 1; j > 0; j >>= 1) {
            for (int i = tid; i < CAP; i += nt) {
                int ixj = i ^ j;
                if (ixj > i) {
                    unsigned long long a = sk[i], b = sk[ixj];
                    bool desc = ((i & k) == 0);
                    if (desc ? (a < b) : (a > b)) { sk[i] = b; sk[ixj] = a; }
                }
            }
            __syncthreads();
        }
    }

    for (int r = tid; r < KCAND; r += nt) {
        unsigned long long key = sk[r];
        unsigned bits = (unsigned)(key >> 32);
        unsigned fidx = 0xFFFFFFFFu - (unsigned)(key & 0xFFFFFFFFull);
        float s = __uint_as_float(bits);
        if (bits == 0u) { s = 0.f; fidx = 0u; }
        int anc = (int)(fidx / NCLS);
        int cls = (int)(fidx - (unsigned)anc * NCLS) + 1;
        const float* d  = g_reg + ((size_t)img * NANCH + anc) * 4;
        const float* pr = priors + (size_t)anc * 4;
        // cx = pri0 + (d0*0.1)*pri2   (exact mul,mul,add rounding like JAX)
        float cx = __fadd_rn(pr[0], __fmul_rn(__fmul_rn(d[0], 0.1f), pr[2]));
        float cy = __fadd_rn(pr[1], __fmul_rn(__fmul_rn(d[1], 0.1f), pr[3]));
        float w  = __fmul_rn(pr[2], expf(fminf(__fmul_rn(d[2], 0.2f), CLIPV)));
        float h  = __fmul_rn(pr[3], expf(fminf(__fmul_rn(d[3], 0.2f), CLIPV)));
        float hw = __fmul_rn(0.5f, w);
        float hh = __fmul_rn(0.5f, h);
        float x1 = fminf(fmaxf(__fsub_rn(cx, hw), 0.f), 300.f);
        float y1 = fminf(fmaxf(__fsub_rn(cy, hh), 0.f), 300.f);
        float x2 = fminf(fmaxf(__fadd_rn(cx, hw), 0.f), 300.f);
        float y2 = fminf(fmaxf(__fadd_rn(cy, hh), 0.f), 300.f);
        bool valid = (s > 0.f) && (x2 > x1) && (y2 > y1);
        int o = img * KCAND + r;
        g_cbox[o * 4 + 0] = x1; g_cbox[o * 4 + 1] = y1;
        g_cbox[o * 4 + 2] = x2; g_cbox[o * 4 + 3] = y2;
        g_cscore[o] = valid ? s : 0.f;
        g_ccls[o] = cls;
        g_ckeep[o] = valid ? 1 : 0;
    }
}

// ---------------- greedy class-aware NMS (exact fori_loop semantics) -------
// Replicates the reference's batched-nms offset (boxes + cls*301) including
// its f32 coordinate quantization.
__global__ void nms_kernel() {
    __shared__ float bx1[KCAND], by1[KCAND], bx2[KCAND], by2[KCAND], ar[KCAND];
    __shared__ int kc[KCAND], kp[KCAND];
    int img = blockIdx.x, tid = threadIdx.x, nt = blockDim.x;
    for (int i = tid; i < KCAND; i += nt) {
        int o = img * KCAND + i;
        int c = g_ccls[o];
        float off = __fmul_rn((float)c, 301.0f);
        float a1 = __fadd_rn(g_cbox[o * 4 + 0], off);
        float a2 = __fadd_rn(g_cbox[o * 4 + 1], off);
        float a3 = __fadd_rn(g_cbox[o * 4 + 2], off);
        float a4 = __fadd_rn(g_cbox[o * 4 + 3], off);
        bx1[i] = a1; by1[i] = a2; bx2[i] = a3; by2[i] = a4;
        ar[i] = __fmul_rn(__fsub_rn(a3, a1), __fsub_rn(a4, a2));
        kc[i] = c;
        kp[i] = g_ckeep[o];
    }
    for (int i = 0; i < KCAND; i++) {
        __syncthreads();
        if (!kp[i]) continue;
        float ix1 = bx1[i], iy1 = by1[i], ix2 = bx2[i], iy2 = by2[i], ia = ar[i];
        int ic = kc[i];
        for (int j = i + 1 + tid; j < KCAND; j += nt) {
            if (kp[j] && kc[j] == ic) {   // cross-class IoU is exactly 0 (bands >=1 apart)
                float w = fmaxf(__fsub_rn(fminf(ix2, bx2[j]), fmaxf(ix1, bx1[j])), 0.f);
                float h = fmaxf(__fsub_rn(fminf(iy2, by2[j]), fmaxf(iy1, by1[j])), 0.f);
                float inter = __fmul_rn(w, h);
                float denom = __fadd_rn(__fsub_rn(__fadd_rn(ia, ar[j]), inter), 1e-9f);
                float iou = __fdiv_rn(inter, denom);
                if (iou > 0.45f) kp[j] = 0;
            }
        }
    }
    __syncthreads();
    for (int i = tid; i < KCAND; i += nt) g_ckeep[img * KCAND + i] = kp[i];
}

// ---------------- final top-200 + output write ----------------
// out layout: [0,12800) boxes, [12800,16000) scores, [16000,19200) classes(as float)
__global__ void final_kernel(float* __restrict__ out) {
    __shared__ unsigned long long key[512];
    int img = blockIdx.x, tid = threadIdx.x;
    if (tid < KCAND) {
        int o = img * KCAND + tid;
        float ms = g_ckeep[o] ? g_cscore[o] : 0.f;
        key[tid] = ((unsigned long long)__float_as_uint(ms) << 32) |
                   (unsigned long long)(0xFFFFFFFFu - (unsigned)tid);
    } else {
        key[tid] = 0ULL;
    }
    __syncthreads();
    for (int k = 2; k <= 512; k <<= 1) {
        for (int j = k >> 1; j > 0; j >>= 1) {
            int ixj = tid ^ j;
            if (ixj > tid) {
                unsigned long long a = key[tid], b = key[ixj];
                if (((tid & k) == 0) ? (a < b) : (a > b)) { key[tid] = b; key[ixj] = a; }
            }
            __syncthreads();
        }
    }
    if (tid < KOUT) {
        unsigned long long kk = key[tid];
        float s = __uint_as_float((unsigned)(kk >> 32));
        unsigned pos = 0xFFFFFFFFu - (unsigned)(kk & 0xFFFFFFFFull);
        int o = img * KCAND + (int)pos;
        int r = img * KOUT + tid;
        out[r * 4 + 0] = g_cbox[o * 4 + 0];
        out[r * 4 + 1] = g_cbox[o * 4 + 1];
        out[r * 4 + 2] = g_cbox[o * 4 + 2];
        out[r * 4 + 3] = g_cbox[o * 4 + 3];
        out[NIMG * KOUT * 4 + r] = s;
        out[NIMG * KOUT * 5 + r] = (s > 0.f) ? (float)g_ccls[o] : 0.f;
    }
}

// ---------------- host launch ----------------
extern "C" void kernel_launch(void* const* d_in, const int* in_sizes, int n_in,
                              void* d_out, int out_size)
{
    (void)out_size;
    // Detect input ordering: grouped (feat0..5, cls pairs, reg pairs) vs
    // interleaved per-scale (setup_inputs dict order).
    int fi[6], cwi[6], cbi[6], rwi[6], rbi[6], pi = 30;
    bool grouped = (n_in > 1 && in_sizes[1] == 5914624);
    for (int i = 0; i < 6; i++) {
        if (grouped) {
            fi[i] = i;            cwi[i] = 6 + 2 * i;  cbi[i] = 7 + 2 * i;
            rwi[i] = 18 + 2 * i;  rbi[i] = 19 + 2 * i;
        } else {
            fi[i] = 5 * i;        cwi[i] = 5 * i + 1;  cbi[i] = 5 * i + 2;
            rwi[i] = 5 * i + 3;   rbi[i] = 5 * i + 4;
        }
    }

    static const int Cs[6]   = {512, 1024, 512, 256, 256, 256};
    static const int Hs[6]   = {38, 19, 10, 5, 3, 1};
    static const int ANs[6]  = {4, 6, 6, 6, 4, 4};
    static const int BASE[6] = {0, 5776, 7942, 8542, 8692, 8728};

    float *p_cls, *p_reg;
    cudaGetSymbolAddress((void**)&p_cls, g_cls);
    cudaGetSymbolAddress((void**)&p_reg, g_reg);

    zero_kernel<<<(NIMG * 65536 + 255) / 256, 256>>>();

    for (int i = 0; i < 6; i++) {
        int C = Cs[i], H = Hs[i], an = ANs[i];
        int N = NIMG * H * H;
        {   // cls head
            int OC = an * NCLS1;
            dim3 grid((N + 63) / 64, (OC + 63) / 64);
            conv_head<<<grid, 256>>>((const float*)d_in[fi[i]], (const float*)d_in[cwi[i]],
                                     (const float*)d_in[cbi[i]], p_cls,
                                     C, H, H, OC, an, NCLS1, BASE[i]);
        }
        {   // reg head
            int OC = an * 4;
            dim3 grid((N + 63) / 64, (OC + 63) / 64);
            conv_head<<<grid, 256>>>((const float*)d_in[fi[i]], (const float*)d_in[rwi[i]],
                                     (const float*)d_in[rbi[i]], p_reg,
                                     C, H, H, OC, an, 4, BASE[i]);
        }
    }

    softmax_kernel<<<(NIMG * NANCH + 7) / 8, 256>>>();

    int tot = NIMG * NANCH * NCLS;
    hist_kernel<<<(tot + 255) / 256, 256>>>();
    select_kernel<<<NIMG, 256>>>();
    compact_kernel<<<(tot + 255) / 256, 256>>>();

    cudaFuncSetAttribute(sort_decode_kernel,
                         cudaFuncAttributeMaxDynamicSharedMemorySize, CAP * 8);
    sort_decode_kernel<<<NIMG, 1024, CAP * 8>>>((const float*)d_in[pi]);

    nms_kernel<<<NIMG, 256>>>();
    final_kernel<<<NIMG, 512>>>((float*)d_out);
}